// round 13
// baseline (speedup 1.0000x reference)
#include <cuda_runtime.h>
#include <cuda_bf16.h>
#include <cstdint>

// ResRnn via warp-level bf16 mma.sync. R13: latency-proofed mainloop.
// 128 CTAs x 512 thr (16 warps = 8 M-warps x 2 K-halves, 128-reg budget).
// A fragments: LDG.128 from fragment-permuted global state, prefetch ring
// depth 4 (8 in-flight LDG.128/warp). 6 independent accumulators kill all
// intra-step RAW chains. Balanced 2-way K-reduction; epilogue split by jg.

#define SEQ    1024
#define BATCH  256
#define INSZ   64
#define SSZ    1024
#define OUTSZ  64
#define NCTA   128
#define NTHR   512
#define NSL    16
#define NSTEP  32        // K-steps per warp (K16 each; warp covers K=512)

// SMEM layout (bytes)
#define W1B    0u
#define W2B    65536u
#define WLO    32768u
#define RED    131072u    // 2 x 4096 exchange
#define BIAS1  139264u
#define BIAS2  139328u
#define SMEM_BYTES 139392u

// Fragment-permuted state: [buf][half][mtile 16][ktile 64][lane*4+reg]
__device__ uint32_t g_SP[2][2][16][64][128];
__device__ uint32_t g_HP[2][16][64][128];
__device__ float    g_Sf[2][BATCH][SSZ];
__device__ unsigned g_grp[16];
__device__ unsigned g_root;
__device__ volatile unsigned g_epoch;

// ---------------- PTX helpers ----------------
__device__ __forceinline__ uint32_t smem_u32(const void* p) {
    uint32_t a;
    asm("{ .reg .u64 t; cvta.to.shared.u64 t, %1; cvt.u32.u64 %0, t; }"
        : "=r"(a) : "l"(p));
    return a;
}
__device__ __forceinline__ void ldsm4(uint32_t a[4], uint32_t addr) {
    asm volatile("ldmatrix.sync.aligned.m8n8.x4.shared.b16 {%0,%1,%2,%3}, [%4];"
        : "=r"(a[0]), "=r"(a[1]), "=r"(a[2]), "=r"(a[3]) : "r"(addr));
}
__device__ __forceinline__ void mma16816(float c[4], const uint4& a,
                                         uint32_t b0, uint32_t b1) {
    asm volatile(
        "mma.sync.aligned.m16n8k16.row.col.f32.bf16.bf16.f32 "
        "{%0,%1,%2,%3}, {%4,%5,%6,%7}, {%8,%9}, {%0,%1,%2,%3};"
        : "+f"(c[0]), "+f"(c[1]), "+f"(c[2]), "+f"(c[3])
        : "r"(a.x), "r"(a.y), "r"(a.z), "r"(a.w), "r"(b0), "r"(b1));
}

// 2-level tree barrier (16 groups x 8), monotonic (graph-replay safe)
__device__ __forceinline__ void gbar(unsigned ep0, unsigned idx, int cta) {
    __syncthreads();
    if (threadIdx.x == 0) {
        __threadfence();
        unsigned o = atomicAdd(&g_grp[cta & 15], 1u);
        if ((o & 7u) == 7u) {
            unsigned r = atomicAdd(&g_root, 1u);
            if ((r & 15u) == 15u) {
                __threadfence();
                atomicAdd((unsigned*)&g_epoch, 1u);
            }
        }
        while ((unsigned)(g_epoch - ep0) < idx) { }
        __threadfence();
    }
    __syncthreads();
}

__device__ __forceinline__ void split_bf(float v, __nv_bfloat16& h, __nv_bfloat16& l) {
    h = __float2bfloat16(v);
    l = __float2bfloat16(v - __bfloat162float(h));
}
__device__ __forceinline__ uint32_t pk(__nv_bfloat16 a, __nv_bfloat16 b) {
    return (uint32_t)__bfloat16_as_ushort(a) | ((uint32_t)__bfloat16_as_ushort(b) << 16);
}

// One warp's K=512 slice: 32 K16-steps. A hi/lo via LDG.128 ring (depth 4);
// W via swizzled ldmatrix; 6 independent fp32 accumulators (no intra-step RAW).
__device__ __forceinline__ void mma_phase(const uint4* __restrict__ ph,
                                          const uint4* __restrict__ pl,
                                          uint32_t wlane, uint32_t nx, uint32_t c16b,
                                          float acc0[4], float acc1[4])
{
    float hh0[4] = {0,0,0,0}, hh1[4] = {0,0,0,0};
    float hl0[4] = {0,0,0,0}, hl1[4] = {0,0,0,0};
    float lh0[4] = {0,0,0,0}, lh1[4] = {0,0,0,0};

    uint4 Ah[4], Al[4];
#pragma unroll
    for (int i = 0; i < 4; ++i) { Ah[i] = ph[i * 32]; Al[i] = pl[i * 32]; }

#pragma unroll 4
    for (int st = 0; st < NSTEP; ++st) {
        const int s = st & 3;
        uint32_t Wh[4], Wl[4];
        const uint32_t wa = wlane + (((c16b + 2u * (uint32_t)st) ^ nx) << 4);
        ldsm4(Wh, wa);
        ldsm4(Wl, wa + WLO);
        const uint4 ah = Ah[s];
        const uint4 al = Al[s];
        if (st + 4 < NSTEP) { Ah[s] = ph[(st + 4) * 32]; Al[s] = pl[(st + 4) * 32]; }
        mma16816(hh0, ah, Wh[0], Wh[1]);
        mma16816(hh1, ah, Wh[2], Wh[3]);
        mma16816(hl0, ah, Wl[0], Wl[1]);
        mma16816(hl1, ah, Wl[2], Wl[3]);
        mma16816(lh0, al, Wh[0], Wh[1]);
        mma16816(lh1, al, Wh[2], Wh[3]);
    }
#pragma unroll
    for (int i = 0; i < 4; ++i) {
        acc0[i] = hh0[i] + hl0[i] + lh0[i];
        acc1[i] = hh1[i] + hl1[i] + lh1[i];
    }
}

// Balanced 2-way K-exchange: jg0 ends with full acc0 (cols 0-7),
// jg1 with full acc1 (cols 8-15).
__device__ __forceinline__ void kreduce(uint32_t su, int jg, int m, int lane,
                                        float acc0[4], float acc1[4]) {
    const uint32_t slot = (uint32_t)(m * 32 + lane) * 16u;
    if (jg == 0) {
        asm volatile("st.shared.v4.f32 [%0], {%1,%2,%3,%4};" ::
            "r"(su + RED + slot),
            "f"(acc1[0]), "f"(acc1[1]), "f"(acc1[2]), "f"(acc1[3]));
    } else {
        asm volatile("st.shared.v4.f32 [%0], {%1,%2,%3,%4};" ::
            "r"(su + RED + 4096u + slot),
            "f"(acc0[0]), "f"(acc0[1]), "f"(acc0[2]), "f"(acc0[3]));
    }
    __syncthreads();
    float r0, r1, r2, r3;
    if (jg == 0) {
        asm volatile("ld.shared.v4.f32 {%0,%1,%2,%3}, [%4];"
            : "=f"(r0), "=f"(r1), "=f"(r2), "=f"(r3)
            : "r"(su + RED + 4096u + slot));
        acc0[0] += r0; acc0[1] += r1; acc0[2] += r2; acc0[3] += r3;
    } else {
        asm volatile("ld.shared.v4.f32 {%0,%1,%2,%3}, [%4];"
            : "=f"(r0), "=f"(r1), "=f"(r2), "=f"(r3)
            : "r"(su + RED + slot));
        acc1[0] += r0; acc1[1] += r1; acc1[2] += r2; acc1[3] += r3;
    }
}

__global__ __launch_bounds__(NTHR, 1)
void resrnn_kernel(const float* __restrict__ x,
                   const float* __restrict__ W1,
                   const float* __restrict__ b1,
                   const float* __restrict__ W2,
                   const float* __restrict__ b2,
                   float* __restrict__ out)
{
    extern __shared__ char smem[];
    const uint32_t su = smem_u32(smem);

    const int tid  = threadIdx.x;
    const int wid  = tid >> 5;
    const int lane = tid & 31;
    const int m    = wid & 7;            // M-warp
    const int jg   = wid >> 3;           // K-half 0/1
    const int cta  = blockIdx.x;
    const int mh   = cta & 1;
    const int n0   = (cta >> 1) * NSL;
    const int mtile = mh * 8 + m;

    const unsigned ep0 = g_epoch;

    // ---- stage W slices: fp32 -> bf16 hi/lo, 2048B rows + XOR-16B swizzle ----
    for (int mi = 0; mi < 2; ++mi) {
        const float* W = mi ? W2 : W1;
        const uint32_t base = mi ? W2B : W1B;
        for (int idx = tid; idx < NSL * SSZ; idx += NTHR) {
            int n = idx >> 10, k = idx & (SSZ - 1);
            float w = W[(size_t)(n0 + n) * SSZ + k];
            __nv_bfloat16 wh, wl; split_bf(w, wh, wl);
            uint32_t o = (uint32_t)n * 2048u
                       + (uint32_t)(((k >> 3) ^ (n & 7)) << 4)
                       + (uint32_t)((k & 7) << 1);
            *(__nv_bfloat16*)(smem + base + o)       = wh;
            *(__nv_bfloat16*)(smem + base + WLO + o) = wl;
        }
    }
    {
        float* b1s = (float*)(smem + BIAS1);
        float* b2s = (float*)(smem + BIAS2);
        if (tid < NSL) { b1s[tid] = b1[n0 + tid]; b2s[tid] = b2[n0 + tid]; }
    }

    // ---- init S0 slice (cols n0..n0+16 of this mh half): [x0, zeros] ----
    for (int idx = tid; idx < 128 * 8; idx += NTHR) {
        int row = idx >> 3, pc = idx & 7;
        int b = mh * 128 + row, k = n0 + 2 * pc;
        float v0 = (k < INSZ)     ? x[(size_t)b * INSZ + k]     : 0.0f;
        float v1 = (k + 1 < INSZ) ? x[(size_t)b * INSZ + k + 1] : 0.0f;
        *(float2*)&g_Sf[0][b][k] = make_float2(v0, v1);
        __nv_bfloat16 h0, l0, h1, l1;
        split_bf(v0, h0, l0); split_bf(v1, h1, l1);
        int mt = b >> 4, rr = b & 15;
        int lt  = (rr & 7) * 4 + (pc & 3);
        int reg = (rr >> 3) + 2 * (pc >> 2);
        g_SP[0][0][mt][k >> 4][lt * 4 + reg] = pk(h0, h1);
        g_SP[0][1][mt][k >> 4][lt * 4 + reg] = pk(l0, l1);
    }
    unsigned bc = 0;
    gbar(ep0, ++bc, cta);

    // ---- per-lane constants ----
    const int lane4 = lane * 4;
    const uint32_t wn   = (uint32_t)((lane & 7) + ((lane >> 4) & 1) * 8);
    const uint32_t nx   = wn & 7u;
    const uint32_t wrow = wn * 2048u;
    const uint32_t c16b = (uint32_t)jg * 64u + (uint32_t)((lane >> 3) & 1);

    const int gr = lane >> 2;
    const int gc = 2 * (lane & 3);
    const float* b1s = (const float*)(smem + BIAS1);
    const float* b2s = (const float*)(smem + BIAS2);
    const float p = 0.97f;
    const float q = 1.0f - 0.97f;
    const int ep_lt = gr * 4 + (lane & 3);   // permuted-store lane slot

    for (int t = 0; t < SEQ; ++t) {
        const int cur = t & 1, nxt = (t + 1) & 1;

        // ============ Phase 1: H = |S @ W1^T + b1| ============
        {
            float acc0[4], acc1[4];
            mma_phase((const uint4*)&g_SP[cur][0][mtile][jg * 32][lane4],
                      (const uint4*)&g_SP[cur][1][mtile][jg * 32][lane4],
                      su + W1B + wrow, nx, c16b, acc0, acc1);
            kreduce(su, jg, m, lane, acc0, acc1);
            {
                const float* acc = jg ? acc1 : acc0;
                const int c = 8 * jg + gc;
                uint32_t* hp = &g_HP[0][mtile][n0 >> 4][ep_lt * 4];
#pragma unroll
                for (int h = 0; h < 2; ++h) {
                    float v0 = fabsf(acc[2 * h]     + b1s[c]);
                    float v1 = fabsf(acc[2 * h + 1] + b1s[c + 1]);
                    __nv_bfloat16 h0, l0, h1, l1;
                    split_bf(v0, h0, l0); split_bf(v1, h1, l1);
                    hp[h + 2 * jg]                 = pk(h0, h1);
                    hp[h + 2 * jg + 16 * 64 * 128] = pk(l0, l1);
                }
            }
        }
        gbar(ep0, ++bc, cta);

        // ============ Phase 2: S' = p*S + q*(H @ W2^T + b2) ============
        {
            float acc0[4], acc1[4];
            mma_phase((const uint4*)&g_HP[0][mtile][jg * 32][lane4],
                      (const uint4*)&g_HP[1][mtile][jg * 32][lane4],
                      su + W2B + wrow, nx, c16b, acc0, acc1);
            kreduce(su, jg, m, lane, acc0, acc1);
            {
                const float* acc = jg ? acc1 : acc0;
                const int c = 8 * jg + gc;
                uint32_t* sph = &g_SP[nxt][0][mtile][(n0 + INSZ) >> 4][ep_lt * 4];
                uint32_t* spl = &g_SP[nxt][1][mtile][(n0 + INSZ) >> 4][ep_lt * 4];
#pragma unroll
                for (int h = 0; h < 2; ++h) {
                    int b = mh * 128 + 16 * m + gr + h * 8;
                    float2 sold = *(const float2*)&g_Sf[cur][b][n0 + c];
                    float n0v = p * sold.x + q * (acc[2 * h]     + b2s[c]);
                    float n1v = p * sold.y + q * (acc[2 * h + 1] + b2s[c + 1]);
                    if (n0 < SSZ - INSZ) {
                        *(float2*)&g_Sf[nxt][b][n0 + INSZ + c] = make_float2(n0v, n1v);
                        __nv_bfloat16 h0, l0, h1, l1;
                        split_bf(n0v, h0, l0); split_bf(n1v, h1, l1);
                        sph[h + 2 * jg] = pk(h0, h1);
                        spl[h + 2 * jg] = pk(l0, l1);
                    }
                    if (t == SEQ - 1 && n0 >= SSZ - OUTSZ) {
                        *(float2*)&out[(size_t)b * OUTSZ + (n0 - (SSZ - OUTSZ)) + c] =
                            make_float2(n0v, n1v);
                    }
                }
            }
            // inject x_{t+1} into cols [n0, n0+16) for n0 < 64 (jg==1 threads)
            if (n0 < INSZ && t + 1 < SEQ && jg == 1) {
                const float* xp = x + (size_t)(t + 1) * BATCH * INSZ;
                for (int idx = tid - 256; idx < 128 * 8; idx += 256) {
                    int row = idx >> 3, pc = idx & 7;
                    int b = mh * 128 + row, k = n0 + 2 * pc;
                    float v0 = xp[(size_t)b * INSZ + k];
                    float v1 = xp[(size_t)b * INSZ + k + 1];
                    *(float2*)&g_Sf[nxt][b][k] = make_float2(v0, v1);
                    __nv_bfloat16 h0, l0, h1, l1;
                    split_bf(v0, h0, l0); split_bf(v1, h1, l1);
                    int mt = b >> 4, rr = b & 15;
                    int lt  = (rr & 7) * 4 + (pc & 3);
                    int reg = (rr >> 3) + 2 * (pc >> 2);
                    g_SP[nxt][0][mt][k >> 4][lt * 4 + reg] = pk(h0, h1);
                    g_SP[nxt][1][mt][k >> 4][lt * 4 + reg] = pk(l0, l1);
                }
            }
        }
        gbar(ep0, ++bc, cta);
    }
}

extern "C" void kernel_launch(void* const* d_in, const int* in_sizes, int n_in,
                              void* d_out, int out_size) {
    (void)in_sizes; (void)n_in; (void)out_size;
    const float* x  = (const float*)d_in[0];
    const float* W1 = (const float*)d_in[1];
    const float* b1 = (const float*)d_in[2];
    const float* W2 = (const float*)d_in[3];
    const float* b2 = (const float*)d_in[4];

    cudaFuncSetAttribute(resrnn_kernel,
                         cudaFuncAttributeMaxDynamicSharedMemorySize,
                         (int)SMEM_BYTES);
    resrnn_kernel<<<NCTA, NTHR, SMEM_BYTES>>>(x, W1, b1, W2, b2, (float*)d_out);
}

// round 14
// speedup vs baseline: 1.1388x; 1.1388x over previous
#include <cuda_runtime.h>
#include <cuda_bf16.h>
#include <cstdint>

// ResRnn via warp-level bf16 mma.sync. R14: L1-wavefront-optimized.
// 128 CTAs x 512 thr; 16 warps = 4 M-groups (M=32: two m-tiles) x 4 K-groups
// (K=256: 16 K16-steps). One W-ldsm pair feeds BOTH m-tiles (12 mma) per step
// => W smem traffic halved vs R12. A via LDG.128 from fragment-permuted
// global state (depth-2 ring). Balanced 4-way K-reduction: K-group jg owns
// (tile jg>>1, n-half jg&1) and does 1/4 of the epilogue. hi/lo bf16 split
// (3 passes, fp32 accum); fp32 master state.

#define SEQ    1024
#define BATCH  256
#define INSZ   64
#define SSZ    1024
#define OUTSZ  64
#define NCTA   128
#define NTHR   512
#define NSL    16
#define NSTEP  16

// SMEM layout (bytes)
#define W1B    0u
#define W2B    65536u
#define WLO    32768u
#define RED    131072u    // 12 slots x 2KB = 24KB
#define BIAS1  155648u
#define BIAS2  155712u
#define SMEM_BYTES 155776u

#define HPLO   (16 * 64 * 128)   // hi->lo word offset inside g_HP

// Fragment-permuted state: [buf][half][mtile 16][ktile 64][lane*4+reg]
__device__ uint32_t g_SP[2][2][16][64][128];
__device__ uint32_t g_HP[2][16][64][128];
__device__ float    g_Sf[2][BATCH][SSZ];
__device__ unsigned g_grp[16];
__device__ unsigned g_root;
__device__ volatile unsigned g_epoch;

// ---------------- PTX helpers ----------------
__device__ __forceinline__ uint32_t smem_u32(const void* p) {
    uint32_t a;
    asm("{ .reg .u64 t; cvta.to.shared.u64 t, %1; cvt.u32.u64 %0, t; }"
        : "=r"(a) : "l"(p));
    return a;
}
__device__ __forceinline__ void ldsm4(uint32_t a[4], uint32_t addr) {
    asm volatile("ldmatrix.sync.aligned.m8n8.x4.shared.b16 {%0,%1,%2,%3}, [%4];"
        : "=r"(a[0]), "=r"(a[1]), "=r"(a[2]), "=r"(a[3]) : "r"(addr));
}
__device__ __forceinline__ void mma16816(float c[4], const uint4& a,
                                         uint32_t b0, uint32_t b1) {
    asm volatile(
        "mma.sync.aligned.m16n8k16.row.col.f32.bf16.bf16.f32 "
        "{%0,%1,%2,%3}, {%4,%5,%6,%7}, {%8,%9}, {%0,%1,%2,%3};"
        : "+f"(c[0]), "+f"(c[1]), "+f"(c[2]), "+f"(c[3])
        : "r"(a.x), "r"(a.y), "r"(a.z), "r"(a.w), "r"(b0), "r"(b1));
}

// 2-level tree barrier (16 groups x 8), monotonic (graph-replay safe)
__device__ __forceinline__ void gbar(unsigned ep0, unsigned idx, int cta) {
    __syncthreads();
    if (threadIdx.x == 0) {
        __threadfence();
        unsigned o = atomicAdd(&g_grp[cta & 15], 1u);
        if ((o & 7u) == 7u) {
            unsigned r = atomicAdd(&g_root, 1u);
            if ((r & 15u) == 15u) {
                __threadfence();
                atomicAdd((unsigned*)&g_epoch, 1u);
            }
        }
        while ((unsigned)(g_epoch - ep0) < idx) { }
        __threadfence();
    }
    __syncthreads();
}

__device__ __forceinline__ void split_bf(float v, __nv_bfloat16& h, __nv_bfloat16& l) {
    h = __float2bfloat16(v);
    l = __float2bfloat16(v - __bfloat162float(h));
}
__device__ __forceinline__ uint32_t pk(__nv_bfloat16 a, __nv_bfloat16 b) {
    return (uint32_t)__bfloat16_as_ushort(a) | ((uint32_t)__bfloat16_as_ushort(b) << 16);
}

// One warp's K=256 x M=32 slice: 16 K16-steps, 2 m-tiles sharing each W frag.
// acc[4]: [t*2+n] for tile t (0/1), n-half n (0/1). Depth-2 LDG ring.
__device__ __forceinline__ void mma_phase(const uint4* __restrict__ ph,
                                          const uint4* __restrict__ pl,
                                          uint32_t wlane, uint32_t nx, uint32_t c16b,
                                          float acc[4][4])
{
#pragma unroll
    for (int i = 0; i < 4; ++i)
#pragma unroll
        for (int j = 0; j < 4; ++j) acc[i][j] = 0.0f;

    uint4 Ah0[2], Al0[2], Ah1[2], Al1[2];   // tile1 at +2048 uint4
    Ah0[0] = ph[0];   Ah1[0] = ph[2048];
    Al0[0] = pl[0];   Al1[0] = pl[2048];
    Ah0[1] = ph[32];  Ah1[1] = ph[2048 + 32];
    Al0[1] = pl[32];  Al1[1] = pl[2048 + 32];

#pragma unroll
    for (int st = 0; st < NSTEP; ++st) {
        const int s = st & 1;
        uint32_t Wh[4], Wl[4];
        const uint32_t wa = wlane + (((c16b + 2u * (uint32_t)st) ^ nx) << 4);
        ldsm4(Wh, wa);
        ldsm4(Wl, wa + WLO);
        // hh pass
        mma16816(acc[0], Ah0[s], Wh[0], Wh[1]);
        mma16816(acc[2], Ah1[s], Wh[0], Wh[1]);
        mma16816(acc[1], Ah0[s], Wh[2], Wh[3]);
        mma16816(acc[3], Ah1[s], Wh[2], Wh[3]);
        // hl pass
        mma16816(acc[0], Ah0[s], Wl[0], Wl[1]);
        mma16816(acc[2], Ah1[s], Wl[0], Wl[1]);
        mma16816(acc[1], Ah0[s], Wl[2], Wl[3]);
        mma16816(acc[3], Ah1[s], Wl[2], Wl[3]);
        if (st + 2 < NSTEP) {
            Ah0[s] = ph[(st + 2) * 32];
            Ah1[s] = ph[(st + 2) * 32 + 2048];
        }
        // lh pass
        mma16816(acc[0], Al0[s], Wh[0], Wh[1]);
        mma16816(acc[2], Al1[s], Wh[0], Wh[1]);
        mma16816(acc[1], Al0[s], Wh[2], Wh[3]);
        mma16816(acc[3], Al1[s], Wh[2], Wh[3]);
        if (st + 2 < NSTEP) {
            Al0[s] = pl[(st + 2) * 32];
            Al1[s] = pl[(st + 2) * 32 + 2048];
        }
    }
}

// Balanced 4-way K-reduction: group jg ends with the full sum for acc[jg].
__device__ __forceinline__ void kreduce(uint32_t su, int jg, int mg, int lane,
                                        float acc[4][4]) {
#pragma unroll
    for (int a = 0; a < 4; ++a) {
        if (a == jg) continue;
        const int p = jg - (jg > a ? 1 : 0);
        const uint32_t o = su + RED +
            (uint32_t)(((a * 3 + p) * 128) + mg * 32 + lane) * 16u;
        asm volatile("st.shared.v4.f32 [%0], {%1,%2,%3,%4};" ::
            "r"(o), "f"(acc[a][0]), "f"(acc[a][1]),
            "f"(acc[a][2]), "f"(acc[a][3]));
    }
    __syncthreads();
#pragma unroll
    for (int p = 0; p < 3; ++p) {
        const uint32_t o = su + RED +
            (uint32_t)(((jg * 3 + p) * 128) + mg * 32 + lane) * 16u;
        float r0, r1, r2, r3;
        asm volatile("ld.shared.v4.f32 {%0,%1,%2,%3}, [%4];"
            : "=f"(r0), "=f"(r1), "=f"(r2), "=f"(r3) : "r"(o));
        acc[jg][0] += r0; acc[jg][1] += r1;
        acc[jg][2] += r2; acc[jg][3] += r3;
    }
}

__global__ __launch_bounds__(NTHR, 1)
void resrnn_kernel(const float* __restrict__ x,
                   const float* __restrict__ W1,
                   const float* __restrict__ b1,
                   const float* __restrict__ W2,
                   const float* __restrict__ b2,
                   float* __restrict__ out)
{
    extern __shared__ char smem[];
    const uint32_t su = smem_u32(smem);

    const int tid  = threadIdx.x;
    const int wid  = tid >> 5;
    const int lane = tid & 31;
    const int mg   = wid & 3;            // M-group: rows 32*mg..+32 (tiles 2mg, 2mg+1)
    const int jg   = wid >> 2;           // K-group: K [jg*256, +256); owns acc[jg]
    const int cta  = blockIdx.x;
    const int mh   = cta & 1;
    const int n0   = (cta >> 1) * NSL;
    const int mt0  = mh * 8 + 2 * mg;    // first mtile of this warp

    const unsigned ep0 = g_epoch;

    // ---- stage W slices: fp32 -> bf16 hi/lo, 2048B rows + XOR-16B swizzle ----
    for (int mi = 0; mi < 2; ++mi) {
        const float* W = mi ? W2 : W1;
        const uint32_t base = mi ? W2B : W1B;
        for (int idx = tid; idx < NSL * SSZ; idx += NTHR) {
            int n = idx >> 10, k = idx & (SSZ - 1);
            float w = W[(size_t)(n0 + n) * SSZ + k];
            __nv_bfloat16 wh, wl; split_bf(w, wh, wl);
            uint32_t o = (uint32_t)n * 2048u
                       + (uint32_t)(((k >> 3) ^ (n & 7)) << 4)
                       + (uint32_t)((k & 7) << 1);
            *(__nv_bfloat16*)(smem + base + o)       = wh;
            *(__nv_bfloat16*)(smem + base + WLO + o) = wl;
        }
    }
    {
        float* b1s = (float*)(smem + BIAS1);
        float* b2s = (float*)(smem + BIAS2);
        if (tid < NSL) { b1s[tid] = b1[n0 + tid]; b2s[tid] = b2[n0 + tid]; }
    }

    // ---- init S0 slice (cols n0..n0+16 of this mh half): [x0, zeros] ----
    for (int idx = tid; idx < 128 * 8; idx += NTHR) {
        int row = idx >> 3, pc = idx & 7;
        int b = mh * 128 + row, k = n0 + 2 * pc;
        float v0 = (k < INSZ)     ? x[(size_t)b * INSZ + k]     : 0.0f;
        float v1 = (k + 1 < INSZ) ? x[(size_t)b * INSZ + k + 1] : 0.0f;
        *(float2*)&g_Sf[0][b][k] = make_float2(v0, v1);
        __nv_bfloat16 h0, l0, h1, l1;
        split_bf(v0, h0, l0); split_bf(v1, h1, l1);
        int mt = b >> 4, rr = b & 15;
        int lt  = (rr & 7) * 4 + (pc & 3);
        int reg = (rr >> 3) + 2 * (pc >> 2);
        g_SP[0][0][mt][k >> 4][lt * 4 + reg] = pk(h0, h1);
        g_SP[0][1][mt][k >> 4][lt * 4 + reg] = pk(l0, l1);
    }
    unsigned bc = 0;
    gbar(ep0, ++bc, cta);

    // ---- per-lane constants ----
    const int lane4 = lane * 4;
    const uint32_t wn   = (uint32_t)((lane & 7) + ((lane >> 4) & 1) * 8);
    const uint32_t nx   = wn & 7u;
    const uint32_t wrow = wn * 2048u;
    const uint32_t c16b = (uint32_t)jg * 32u + (uint32_t)((lane >> 3) & 1);

    const int gr = lane >> 2;
    const int gc = 2 * (lane & 3);
    const float* b1s = (const float*)(smem + BIAS1);
    const float* b2s = (const float*)(smem + BIAS2);
    const float p = 0.97f;
    const float q = 1.0f - 0.97f;
    const int ep_lt = gr * 4 + (lane & 3);
    const int to = jg >> 1, no = jg & 1;         // owned (tile, n-half)
    const int mtc  = 2 * mg + to;                // owned m-tile (CTA-local)
    const int mtep = mh * 8 + mtc;               // owned global mtile
    const int cown = 8 * no + gc;                // owned column base

    for (int t = 0; t < SEQ; ++t) {
        const int cur = t & 1, nxt = (t + 1) & 1;

        // ============ Phase 1: H = |S @ W1^T + b1| ============
        {
            float acc[4][4];
            mma_phase((const uint4*)&g_SP[cur][0][mt0][jg * 16][lane4],
                      (const uint4*)&g_SP[cur][1][mt0][jg * 16][lane4],
                      su + W1B + wrow, nx, c16b, acc);
            kreduce(su, jg, mg, lane, acc);
            uint32_t* hp = &g_HP[0][mtep][n0 >> 4][ep_lt * 4];
#pragma unroll
            for (int h = 0; h < 2; ++h) {
                float v0 = fabsf(acc[jg][2 * h]     + b1s[cown]);
                float v1 = fabsf(acc[jg][2 * h + 1] + b1s[cown + 1]);
                __nv_bfloat16 h0, l0, h1, l1;
                split_bf(v0, h0, l0); split_bf(v1, h1, l1);
                hp[h + 2 * no]        = pk(h0, h1);
                hp[h + 2 * no + HPLO] = pk(l0, l1);
            }
        }
        gbar(ep0, ++bc, cta);

        // ============ Phase 2: S' = p*S + q*(H @ W2^T + b2) ============
        {
            float acc[4][4];
            mma_phase((const uint4*)&g_HP[0][mt0][jg * 16][lane4],
                      (const uint4*)&g_HP[1][mt0][jg * 16][lane4],
                      su + W2B + wrow, nx, c16b, acc);
            kreduce(su, jg, mg, lane, acc);
            {
                uint32_t* sph = &g_SP[nxt][0][mtep][(n0 + INSZ) >> 4][ep_lt * 4];
                uint32_t* spl = &g_SP[nxt][1][mtep][(n0 + INSZ) >> 4][ep_lt * 4];
#pragma unroll
                for (int h = 0; h < 2; ++h) {
                    int b = mh * 128 + 16 * mtc + gr + h * 8;
                    float2 sold = *(const float2*)&g_Sf[cur][b][n0 + cown];
                    float n0v = p * sold.x + q * (acc[jg][2 * h]     + b2s[cown]);
                    float n1v = p * sold.y + q * (acc[jg][2 * h + 1] + b2s[cown + 1]);
                    if (n0 < SSZ - INSZ) {
                        *(float2*)&g_Sf[nxt][b][n0 + INSZ + cown] = make_float2(n0v, n1v);
                        __nv_bfloat16 h0, l0, h1, l1;
                        split_bf(n0v, h0, l0); split_bf(n1v, h1, l1);
                        sph[h + 2 * no] = pk(h0, h1);
                        spl[h + 2 * no] = pk(l0, l1);
                    }
                    if (t == SEQ - 1 && n0 >= SSZ - OUTSZ) {
                        *(float2*)&out[(size_t)b * OUTSZ + (n0 - (SSZ - OUTSZ)) + cown] =
                            make_float2(n0v, n1v);
                    }
                }
            }
            // x_{t+1} injection: EVERY CTA writes 2 rows x 64 cols (balanced).
            if (t + 1 < SEQ && tid < 64) {
                const int qd  = cta >> 1;
                const int row = 2 * qd + (tid >> 5);
                const int pcq = tid & 31;
                const int b   = mh * 128 + row;
                const int k   = 2 * pcq;
                const float* xp = x + (size_t)(t + 1) * BATCH * INSZ
                                    + (size_t)b * INSZ + k;
                float v0 = xp[0], v1 = xp[1];
                *(float2*)&g_Sf[nxt][b][k] = make_float2(v0, v1);
                __nv_bfloat16 h0, l0, h1, l1;
                split_bf(v0, h0, l0); split_bf(v1, h1, l1);
                int mt = b >> 4, rr = b & 15;
                int pcl = pcq & 7;
                int lt  = (rr & 7) * 4 + (pcl & 3);
                int reg = (rr >> 3) + 2 * (pcl >> 2);
                g_SP[nxt][0][mt][pcq >> 3][lt * 4 + reg] = pk(h0, h1);
                g_SP[nxt][1][mt][pcq >> 3][lt * 4 + reg] = pk(l0, l1);
            }
        }
        gbar(ep0, ++bc, cta);
    }
}

extern "C" void kernel_launch(void* const* d_in, const int* in_sizes, int n_in,
                              void* d_out, int out_size) {
    (void)in_sizes; (void)n_in; (void)out_size;
    const float* x  = (const float*)d_in[0];
    const float* W1 = (const float*)d_in[1];
    const float* b1 = (const float*)d_in[2];
    const float* W2 = (const float*)d_in[3];
    const float* b2 = (const float*)d_in[4];

    cudaFuncSetAttribute(resrnn_kernel,
                         cudaFuncAttributeMaxDynamicSharedMemorySize,
                         (int)SMEM_BYTES);
    resrnn_kernel<<<NCTA, NTHR, SMEM_BYTES>>>(x, W1, b1, W2, b2, (float*)d_out);
}

// round 15
// speedup vs baseline: 1.3716x; 1.2044x over previous
#include <cuda_runtime.h>
#include <cuda_bf16.h>
#include <cstdint>

// ResRnn via warp-level bf16 mma.sync. R15: 2-pass precision split.
// A (state/hidden) kept in bf16-hi ONLY (the banked precision margin pays
// for it: dropped term ~2^-9, attenuation ~2^-2 => rel_err ~4e-4 < 1e-3).
// W keeps hi+lo in SMEM. Per warp-step: 2 LDG.128 (A, 2 m-tiles) + 2 W-ldsm
// + 8 MMA. Ring depth 4. 128 CTAs x 512 thr; 16 warps = 4 M-groups (M=32)
// x 4 K-groups; balanced 4-way K-reduction; fp32 master state.

#define SEQ    1024
#define BATCH  256
#define INSZ   64
#define SSZ    1024
#define OUTSZ  64
#define NCTA   128
#define NTHR   512
#define NSL    16
#define NSTEP  16

// SMEM layout (bytes)
#define W1B    0u
#define W2B    65536u
#define WLO    32768u
#define RED    131072u    // 12 slots x 2KB = 24KB
#define BIAS1  155648u
#define BIAS2  155712u
#define SMEM_BYTES 155776u

// Fragment-permuted state (bf16-hi only): [buf][mtile 16][ktile 64][lane*4+reg]
__device__ uint32_t g_SP[2][16][64][128];
__device__ uint32_t g_HP[16][64][128];
__device__ float    g_Sf[2][BATCH][SSZ];
__device__ unsigned g_grp[16];
__device__ unsigned g_root;
__device__ volatile unsigned g_epoch;

// ---------------- PTX helpers ----------------
__device__ __forceinline__ uint32_t smem_u32(const void* p) {
    uint32_t a;
    asm("{ .reg .u64 t; cvta.to.shared.u64 t, %1; cvt.u32.u64 %0, t; }"
        : "=r"(a) : "l"(p));
    return a;
}
__device__ __forceinline__ void ldsm4(uint32_t a[4], uint32_t addr) {
    asm volatile("ldmatrix.sync.aligned.m8n8.x4.shared.b16 {%0,%1,%2,%3}, [%4];"
        : "=r"(a[0]), "=r"(a[1]), "=r"(a[2]), "=r"(a[3]) : "r"(addr));
}
__device__ __forceinline__ void mma16816(float c[4], const uint4& a,
                                         uint32_t b0, uint32_t b1) {
    asm volatile(
        "mma.sync.aligned.m16n8k16.row.col.f32.bf16.bf16.f32 "
        "{%0,%1,%2,%3}, {%4,%5,%6,%7}, {%8,%9}, {%0,%1,%2,%3};"
        : "+f"(c[0]), "+f"(c[1]), "+f"(c[2]), "+f"(c[3])
        : "r"(a.x), "r"(a.y), "r"(a.z), "r"(a.w), "r"(b0), "r"(b1));
}

// 2-level tree barrier (16 groups x 8), monotonic (graph-replay safe)
__device__ __forceinline__ void gbar(unsigned ep0, unsigned idx, int cta) {
    __syncthreads();
    if (threadIdx.x == 0) {
        __threadfence();
        unsigned o = atomicAdd(&g_grp[cta & 15], 1u);
        if ((o & 7u) == 7u) {
            unsigned r = atomicAdd(&g_root, 1u);
            if ((r & 15u) == 15u) {
                __threadfence();
                atomicAdd((unsigned*)&g_epoch, 1u);
            }
        }
        while ((unsigned)(g_epoch - ep0) < idx) { }
        __threadfence();
    }
    __syncthreads();
}

__device__ __forceinline__ void split_bf(float v, __nv_bfloat16& h, __nv_bfloat16& l) {
    h = __float2bfloat16(v);
    l = __float2bfloat16(v - __bfloat162float(h));
}
__device__ __forceinline__ uint32_t pk(__nv_bfloat16 a, __nv_bfloat16 b) {
    return (uint32_t)__bfloat16_as_ushort(a) | ((uint32_t)__bfloat16_as_ushort(b) << 16);
}
__device__ __forceinline__ uint32_t pkf(float a, float b) {
    return pk(__float2bfloat16(a), __float2bfloat16(b));
}

// One warp's K=256 x M=32 slice: 16 K16-steps, 2 m-tiles sharing each W frag.
// A bf16-hi only via depth-4 LDG.128 ring; 2 passes (Wh, Wl) = 8 MMA/step.
__device__ __forceinline__ void mma_phase(const uint4* __restrict__ ph,
                                          uint32_t wlane, uint32_t nx, uint32_t c16b,
                                          float acc[4][4])
{
#pragma unroll
    for (int i = 0; i < 4; ++i)
#pragma unroll
        for (int j = 0; j < 4; ++j) acc[i][j] = 0.0f;

    uint4 A0[4], A1[4];                 // tile1 at +2048 uint4
#pragma unroll
    for (int i = 0; i < 4; ++i) { A0[i] = ph[i * 32]; A1[i] = ph[i * 32 + 2048]; }

#pragma unroll
    for (int st = 0; st < NSTEP; ++st) {
        const int s = st & 3;
        uint32_t Wh[4], Wl[4];
        const uint32_t wa = wlane + (((c16b + 2u * (uint32_t)st) ^ nx) << 4);
        ldsm4(Wh, wa);
        ldsm4(Wl, wa + WLO);
        const uint4 a0 = A0[s];
        const uint4 a1 = A1[s];
        if (st + 4 < NSTEP) {
            A0[s] = ph[(st + 4) * 32];
            A1[s] = ph[(st + 4) * 32 + 2048];
        }
        // hi*Wh pass
        mma16816(acc[0], a0, Wh[0], Wh[1]);
        mma16816(acc[2], a1, Wh[0], Wh[1]);
        mma16816(acc[1], a0, Wh[2], Wh[3]);
        mma16816(acc[3], a1, Wh[2], Wh[3]);
        // hi*Wl pass
        mma16816(acc[0], a0, Wl[0], Wl[1]);
        mma16816(acc[2], a1, Wl[0], Wl[1]);
        mma16816(acc[1], a0, Wl[2], Wl[3]);
        mma16816(acc[3], a1, Wl[2], Wl[3]);
    }
}

// Balanced 4-way K-reduction: group jg ends with the full sum for acc[jg].
__device__ __forceinline__ void kreduce(uint32_t su, int jg, int mg, int lane,
                                        float acc[4][4]) {
#pragma unroll
    for (int a = 0; a < 4; ++a) {
        if (a == jg) continue;
        const int p = jg - (jg > a ? 1 : 0);
        const uint32_t o = su + RED +
            (uint32_t)(((a * 3 + p) * 128) + mg * 32 + lane) * 16u;
        asm volatile("st.shared.v4.f32 [%0], {%1,%2,%3,%4};" ::
            "r"(o), "f"(acc[a][0]), "f"(acc[a][1]),
            "f"(acc[a][2]), "f"(acc[a][3]));
    }
    __syncthreads();
#pragma unroll
    for (int p = 0; p < 3; ++p) {
        const uint32_t o = su + RED +
            (uint32_t)(((jg * 3 + p) * 128) + mg * 32 + lane) * 16u;
        float r0, r1, r2, r3;
        asm volatile("ld.shared.v4.f32 {%0,%1,%2,%3}, [%4];"
            : "=f"(r0), "=f"(r1), "=f"(r2), "=f"(r3) : "r"(o));
        acc[jg][0] += r0; acc[jg][1] += r1;
        acc[jg][2] += r2; acc[jg][3] += r3;
    }
}

__global__ __launch_bounds__(NTHR, 1)
void resrnn_kernel(const float* __restrict__ x,
                   const float* __restrict__ W1,
                   const float* __restrict__ b1,
                   const float* __restrict__ W2,
                   const float* __restrict__ b2,
                   float* __restrict__ out)
{
    extern __shared__ char smem[];
    const uint32_t su = smem_u32(smem);

    const int tid  = threadIdx.x;
    const int wid  = tid >> 5;
    const int lane = tid & 31;
    const int mg   = wid & 3;            // M-group: rows 32*mg..+32
    const int jg   = wid >> 2;           // K-group: K [jg*256, +256)
    const int cta  = blockIdx.x;
    const int mh   = cta & 1;
    const int n0   = (cta >> 1) * NSL;
    const int mt0  = mh * 8 + 2 * mg;

    const unsigned ep0 = g_epoch;

    // ---- stage W slices: fp32 -> bf16 hi/lo, 2048B rows + XOR-16B swizzle ----
    for (int mi = 0; mi < 2; ++mi) {
        const float* W = mi ? W2 : W1;
        const uint32_t base = mi ? W2B : W1B;
        for (int idx = tid; idx < NSL * SSZ; idx += NTHR) {
            int n = idx >> 10, k = idx & (SSZ - 1);
            float w = W[(size_t)(n0 + n) * SSZ + k];
            __nv_bfloat16 wh, wl; split_bf(w, wh, wl);
            uint32_t o = (uint32_t)n * 2048u
                       + (uint32_t)(((k >> 3) ^ (n & 7)) << 4)
                       + (uint32_t)((k & 7) << 1);
            *(__nv_bfloat16*)(smem + base + o)       = wh;
            *(__nv_bfloat16*)(smem + base + WLO + o) = wl;
        }
    }
    {
        float* b1s = (float*)(smem + BIAS1);
        float* b2s = (float*)(smem + BIAS2);
        if (tid < NSL) { b1s[tid] = b1[n0 + tid]; b2s[tid] = b2[n0 + tid]; }
    }

    // ---- init S0 slice (cols n0..n0+16 of this mh half): [x0, zeros] ----
    for (int idx = tid; idx < 128 * 8; idx += NTHR) {
        int row = idx >> 3, pc = idx & 7;
        int b = mh * 128 + row, k = n0 + 2 * pc;
        float v0 = (k < INSZ)     ? x[(size_t)b * INSZ + k]     : 0.0f;
        float v1 = (k + 1 < INSZ) ? x[(size_t)b * INSZ + k + 1] : 0.0f;
        *(float2*)&g_Sf[0][b][k] = make_float2(v0, v1);
        int mt = b >> 4, rr = b & 15;
        int lt  = (rr & 7) * 4 + (pc & 3);
        int reg = (rr >> 3) + 2 * (pc >> 2);
        g_SP[0][mt][k >> 4][lt * 4 + reg] = pkf(v0, v1);
    }
    unsigned bc = 0;
    gbar(ep0, ++bc, cta);

    // ---- per-lane constants ----
    const int lane4 = lane * 4;
    const uint32_t wn   = (uint32_t)((lane & 7) + ((lane >> 4) & 1) * 8);
    const uint32_t nx   = wn & 7u;
    const uint32_t wrow = wn * 2048u;
    const uint32_t c16b = (uint32_t)jg * 32u + (uint32_t)((lane >> 3) & 1);

    const int gr = lane >> 2;
    const int gc = 2 * (lane & 3);
    const float* b1s = (const float*)(smem + BIAS1);
    const float* b2s = (const float*)(smem + BIAS2);
    const float p = 0.97f;
    const float q = 1.0f - 0.97f;
    const int ep_lt = gr * 4 + (lane & 3);
    const int to = jg >> 1, no = jg & 1;         // owned (tile, n-half)
    const int mtc  = 2 * mg + to;
    const int mtep = mh * 8 + mtc;
    const int cown = 8 * no + gc;

    for (int t = 0; t < SEQ; ++t) {
        const int cur = t & 1, nxt = (t + 1) & 1;

        // ============ Phase 1: H = |S @ W1^T + b1| ============
        {
            float acc[4][4];
            mma_phase((const uint4*)&g_SP[cur][mt0][jg * 16][lane4],
                      su + W1B + wrow, nx, c16b, acc);
            kreduce(su, jg, mg, lane, acc);
            uint32_t* hp = &g_HP[mtep][n0 >> 4][ep_lt * 4];
#pragma unroll
            for (int h = 0; h < 2; ++h) {
                float v0 = fabsf(acc[jg][2 * h]     + b1s[cown]);
                float v1 = fabsf(acc[jg][2 * h + 1] + b1s[cown + 1]);
                hp[h + 2 * no] = pkf(v0, v1);
            }
        }
        gbar(ep0, ++bc, cta);

        // ============ Phase 2: S' = p*S + q*(H @ W2^T + b2) ============
        {
            float acc[4][4];
            mma_phase((const uint4*)&g_HP[mt0][jg * 16][lane4],
                      su + W2B + wrow, nx, c16b, acc);
            kreduce(su, jg, mg, lane, acc);
            {
                uint32_t* sph = &g_SP[nxt][mtep][(n0 + INSZ) >> 4][ep_lt * 4];
#pragma unroll
                for (int h = 0; h < 2; ++h) {
                    int b = mh * 128 + 16 * mtc + gr + h * 8;
                    float2 sold = *(const float2*)&g_Sf[cur][b][n0 + cown];
                    float n0v = p * sold.x + q * (acc[jg][2 * h]     + b2s[cown]);
                    float n1v = p * sold.y + q * (acc[jg][2 * h + 1] + b2s[cown + 1]);
                    if (n0 < SSZ - INSZ) {
                        *(float2*)&g_Sf[nxt][b][n0 + INSZ + cown] = make_float2(n0v, n1v);
                        sph[h + 2 * no] = pkf(n0v, n1v);
                    }
                    if (t == SEQ - 1 && n0 >= SSZ - OUTSZ) {
                        *(float2*)&out[(size_t)b * OUTSZ + (n0 - (SSZ - OUTSZ)) + cown] =
                            make_float2(n0v, n1v);
                    }
                }
            }
            // x_{t+1} injection: every CTA writes 2 rows x 64 cols (balanced).
            if (t + 1 < SEQ && tid < 64) {
                const int qd  = cta >> 1;
                const int row = 2 * qd + (tid >> 5);
                const int pcq = tid & 31;
                const int b   = mh * 128 + row;
                const int k   = 2 * pcq;
                const float* xp = x + (size_t)(t + 1) * BATCH * INSZ
                                    + (size_t)b * INSZ + k;
                float v0 = xp[0], v1 = xp[1];
                *(float2*)&g_Sf[nxt][b][k] = make_float2(v0, v1);
                int mt = b >> 4, rr = b & 15;
                int pcl = pcq & 7;
                int lt  = (rr & 7) * 4 + (pcl & 3);
                int reg = (rr >> 3) + 2 * (pcl >> 2);
                g_SP[nxt][mt][pcq >> 3][lt * 4 + reg] = pkf(v0, v1);
            }
        }
        gbar(ep0, ++bc, cta);
    }
}

extern "C" void kernel_launch(void* const* d_in, const int* in_sizes, int n_in,
                              void* d_out, int out_size) {
    (void)in_sizes; (void)n_in; (void)out_size;
    const float* x  = (const float*)d_in[0];
    const float* W1 = (const float*)d_in[1];
    const float* b1 = (const float*)d_in[2];
    const float* W2 = (const float*)d_in[3];
    const float* b2 = (const float*)d_in[4];

    cudaFuncSetAttribute(resrnn_kernel,
                         cudaFuncAttributeMaxDynamicSharedMemorySize,
                         (int)SMEM_BYTES);
    resrnn_kernel<<<NCTA, NTHR, SMEM_BYTES>>>(x, W1, b1, W2, b2, (float*)d_out);
}

// round 16
// speedup vs baseline: 1.4476x; 1.0554x over previous
#include <cuda_runtime.h>
#include <cuda_bf16.h>
#include <cstdint>

// ResRnn via warp-level bf16 mma.sync. R16: L2-traffic-halved retile.
// Grid 128 = 4 M-slices x 32 N-slices; CTA = 64 rows x 32 cols => each CTA
// reads only 128KB of A per phase (A traffic 32MB/step, half of R15).
// W SMEM = W1 hi+lo + W2 hi (192KB); phase2 is 1-pass (W2-lo dropped,
// spending calibrated precision margin: predicted rel_err ~5e-4 < 1e-3).
// 512 thr; 16 warps = 4 M-groups (M=16) x 4 K-groups (K=256). A via LDG.128
// ring depth 4 from fragment-permuted state; fp32 master state.

#define SEQ    1024
#define BATCH  256
#define INSZ   64
#define SSZ    1024
#define OUTSZ  64
#define NCTA   128
#define NTHR   512
#define NSL    32        // cols per CTA
#define NSTEP  16

// SMEM layout (bytes): 3 W planes (32 rows x 2048B, XOR-swizzled)
#define W1HB   0u
#define W1LB   65536u
#define W2HB   131072u
#define WCH23  32768u    // rows 16..31 (n-chunks 2,3) offset within a plane
#define RED    196608u   // 12 x 128 x 16B = 24KB
#define BIAS1  221184u
#define BIAS2  221312u
#define SMEM_BYTES 221440u

// Fragment-permuted state (bf16-hi): [buf][mtile 16][ktile 64][lane*4+reg]
__device__ uint32_t g_SP[2][16][64][128];
__device__ uint32_t g_HP[16][64][128];
__device__ float    g_Sf[2][BATCH][SSZ];
__device__ unsigned g_grp[16];
__device__ unsigned g_root;
__device__ volatile unsigned g_epoch;

// ---------------- PTX helpers ----------------
__device__ __forceinline__ uint32_t smem_u32(const void* p) {
    uint32_t a;
    asm("{ .reg .u64 t; cvta.to.shared.u64 t, %1; cvt.u32.u64 %0, t; }"
        : "=r"(a) : "l"(p));
    return a;
}
__device__ __forceinline__ void ldsm4(uint32_t a[4], uint32_t addr) {
    asm volatile("ldmatrix.sync.aligned.m8n8.x4.shared.b16 {%0,%1,%2,%3}, [%4];"
        : "=r"(a[0]), "=r"(a[1]), "=r"(a[2]), "=r"(a[3]) : "r"(addr));
}
__device__ __forceinline__ void mma16816(float c[4], const uint4& a,
                                         uint32_t b0, uint32_t b1) {
    asm volatile(
        "mma.sync.aligned.m16n8k16.row.col.f32.bf16.bf16.f32 "
        "{%0,%1,%2,%3}, {%4,%5,%6,%7}, {%8,%9}, {%0,%1,%2,%3};"
        : "+f"(c[0]), "+f"(c[1]), "+f"(c[2]), "+f"(c[3])
        : "r"(a.x), "r"(a.y), "r"(a.z), "r"(a.w), "r"(b0), "r"(b1));
}

// 2-level tree barrier (16 groups x 8), monotonic (graph-replay safe)
__device__ __forceinline__ void gbar(unsigned ep0, unsigned idx, int cta) {
    __syncthreads();
    if (threadIdx.x == 0) {
        __threadfence();
        unsigned o = atomicAdd(&g_grp[cta & 15], 1u);
        if ((o & 7u) == 7u) {
            unsigned r = atomicAdd(&g_root, 1u);
            if ((r & 15u) == 15u) {
                __threadfence();
                atomicAdd((unsigned*)&g_epoch, 1u);
            }
        }
        while ((unsigned)(g_epoch - ep0) < idx) { }
        __threadfence();
    }
    __syncthreads();
}

__device__ __forceinline__ void split_bf(float v, __nv_bfloat16& h, __nv_bfloat16& l) {
    h = __float2bfloat16(v);
    l = __float2bfloat16(v - __bfloat162float(h));
}
__device__ __forceinline__ uint32_t pk(__nv_bfloat16 a, __nv_bfloat16 b) {
    return (uint32_t)__bfloat16_as_ushort(a) | ((uint32_t)__bfloat16_as_ushort(b) << 16);
}
__device__ __forceinline__ uint32_t pkf(float a, float b) {
    return pk(__float2bfloat16(a), __float2bfloat16(b));
}

// One warp's M=16 x N=32 x K=256 slice. A via depth-4 LDG.128 ring.
// PASSES=2: hi*Wh + hi*Wl (phase 1). PASSES=1: hi*Wh only (phase 2).
template <int PASSES>
__device__ __forceinline__ void mma_phase(const uint4* __restrict__ pa,
                                          uint32_t whl, uint32_t wll,
                                          uint32_t nx, uint32_t c16b,
                                          float acc[4][4])
{
#pragma unroll
    for (int i = 0; i < 4; ++i)
#pragma unroll
        for (int j = 0; j < 4; ++j) acc[i][j] = 0.0f;

    uint4 A[4];
#pragma unroll
    for (int i = 0; i < 4; ++i) A[i] = pa[i * 32];

#pragma unroll
    for (int st = 0; st < NSTEP; ++st) {
        const int s = st & 3;
        const uint32_t sw = (((c16b + 2u * (uint32_t)st) ^ nx) << 4);
        uint32_t WhA[4], WhB[4];
        ldsm4(WhA, whl + sw);
        ldsm4(WhB, whl + WCH23 + sw);
        const uint4 a = A[s];
        if (st + 4 < NSTEP) A[s] = pa[(st + 4) * 32];
        mma16816(acc[0], a, WhA[0], WhA[1]);
        mma16816(acc[1], a, WhA[2], WhA[3]);
        mma16816(acc[2], a, WhB[0], WhB[1]);
        mma16816(acc[3], a, WhB[2], WhB[3]);
        if (PASSES == 2) {
            uint32_t WlA[4], WlB[4];
            ldsm4(WlA, wll + sw);
            ldsm4(WlB, wll + WCH23 + sw);
            mma16816(acc[0], a, WlA[0], WlA[1]);
            mma16816(acc[1], a, WlA[2], WlA[3]);
            mma16816(acc[2], a, WlB[0], WlB[1]);
            mma16816(acc[3], a, WlB[2], WlB[3]);
        }
    }
}

// Balanced 4-way K-reduction: group jg ends with the full sum for acc[jg].
__device__ __forceinline__ void kreduce(uint32_t su, int jg, int mg, int lane,
                                        float acc[4][4]) {
#pragma unroll
    for (int a = 0; a < 4; ++a) {
        if (a == jg) continue;
        const int p = jg - (jg > a ? 1 : 0);
        const uint32_t o = su + RED +
            (uint32_t)(((a * 3 + p) * 128) + mg * 32 + lane) * 16u;
        asm volatile("st.shared.v4.f32 [%0], {%1,%2,%3,%4};" ::
            "r"(o), "f"(acc[a][0]), "f"(acc[a][1]),
            "f"(acc[a][2]), "f"(acc[a][3]));
    }
    __syncthreads();
#pragma unroll
    for (int p = 0; p < 3; ++p) {
        const uint32_t o = su + RED +
            (uint32_t)(((jg * 3 + p) * 128) + mg * 32 + lane) * 16u;
        float r0, r1, r2, r3;
        asm volatile("ld.shared.v4.f32 {%0,%1,%2,%3}, [%4];"
            : "=f"(r0), "=f"(r1), "=f"(r2), "=f"(r3) : "r"(o));
        acc[jg][0] += r0; acc[jg][1] += r1;
        acc[jg][2] += r2; acc[jg][3] += r3;
    }
}

__global__ __launch_bounds__(NTHR, 1)
void resrnn_kernel(const float* __restrict__ x,
                   const float* __restrict__ W1,
                   const float* __restrict__ b1,
                   const float* __restrict__ W2,
                   const float* __restrict__ b2,
                   float* __restrict__ out)
{
    extern __shared__ char smem[];
    const uint32_t su = smem_u32(smem);

    const int tid  = threadIdx.x;
    const int wid  = tid >> 5;
    const int lane = tid & 31;
    const int mg   = wid & 3;            // M-group: mtile 4*ms+mg
    const int jg   = wid >> 2;           // K-group: K [jg*256, +256)
    const int cta  = blockIdx.x;
    const int ms   = cta & 3;            // M-slice: rows 64*ms..+64
    const int ns   = cta >> 2;           // N-slice: cols 32*ns..+32
    const int n0   = ns * NSL;
    const int mt   = 4 * ms + mg;        // this warp's mtile (A + epilogue)

    const unsigned ep0 = g_epoch;

    // ---- stage W slices: W1 hi+lo, W2 hi (2048B rows + XOR-16B swizzle) ----
    for (int idx = tid; idx < NSL * SSZ; idx += NTHR) {
        int n = idx >> 10, k = idx & (SSZ - 1);
        uint32_t o = (uint32_t)n * 2048u
                   + (uint32_t)(((k >> 3) ^ (n & 7)) << 4)
                   + (uint32_t)((k & 7) << 1);
        float w1 = W1[(size_t)(n0 + n) * SSZ + k];
        __nv_bfloat16 wh, wl; split_bf(w1, wh, wl);
        *(__nv_bfloat16*)(smem + W1HB + o) = wh;
        *(__nv_bfloat16*)(smem + W1LB + o) = wl;
        float w2 = W2[(size_t)(n0 + n) * SSZ + k];
        *(__nv_bfloat16*)(smem + W2HB + o) = __float2bfloat16(w2);
    }
    {
        float* b1s = (float*)(smem + BIAS1);
        float* b2s = (float*)(smem + BIAS2);
        if (tid < NSL) { b1s[tid] = b1[n0 + tid]; b2s[tid] = b2[n0 + tid]; }
    }

    // ---- init S0 (this CTA's 64 rows x 32 cols): [x0, zeros] ----
    for (int idx = tid; idx < 64 * 16; idx += NTHR) {
        int row = idx >> 4, pc = idx & 15;
        int b = 64 * ms + row, k = n0 + 2 * pc;
        float v0 = (k < INSZ)     ? x[(size_t)b * INSZ + k]     : 0.0f;
        float v1 = (k + 1 < INSZ) ? x[(size_t)b * INSZ + k + 1] : 0.0f;
        *(float2*)&g_Sf[0][b][k] = make_float2(v0, v1);
        int bt = b >> 4, rr = b & 15, c = k & 15;
        int lt  = (rr & 7) * 4 + ((c >> 1) & 3);
        int reg = (rr >> 3) + 2 * (c >> 3);
        g_SP[0][bt][k >> 4][lt * 4 + reg] = pkf(v0, v1);
    }
    unsigned bc = 0;
    gbar(ep0, ++bc, cta);

    // ---- per-lane constants ----
    const int lane4 = lane * 4;
    const uint32_t wn   = (uint32_t)((lane & 7) + ((lane >> 4) & 1) * 8);
    const uint32_t nx   = wn & 7u;
    const uint32_t wrow = wn * 2048u;
    const uint32_t c16b = (uint32_t)jg * 32u + (uint32_t)((lane >> 3) & 1);

    const int gr = lane >> 2;
    const int gc = 2 * (lane & 3);
    const float* b1s = (const float*)(smem + BIAS1);
    const float* b2s = (const float*)(smem + BIAS2);
    const float p = 0.97f;
    const float q = 1.0f - 0.97f;
    const int ep_lt = gr * 4 + (lane & 3);
    const int no   = jg & 1;                 // n-half within owned ktile
    const int cown = 8 * jg + gc;            // owned slice-local col base

    for (int t = 0; t < SEQ; ++t) {
        const int cur = t & 1, nxt = (t + 1) & 1;

        // ============ Phase 1: H = |S @ W1^T + b1| ============
        {
            float acc[4][4];
            mma_phase<2>((const uint4*)&g_SP[cur][mt][jg * 16][lane4],
                         su + W1HB + wrow, su + W1LB + wrow, nx, c16b, acc);
            kreduce(su, jg, mg, lane, acc);
            const int kt = 2 * ns + (jg >> 1);
            uint32_t* hp = &g_HP[mt][kt][ep_lt * 4];
#pragma unroll
            for (int h = 0; h < 2; ++h) {
                float v0 = fabsf(acc[jg][2 * h]     + b1s[cown]);
                float v1 = fabsf(acc[jg][2 * h + 1] + b1s[cown + 1]);
                hp[h + 2 * no] = pkf(v0, v1);
            }
        }
        gbar(ep0, ++bc, cta);

        // ============ Phase 2: S' = p*S + q*(H @ W2^T + b2) ============
        {
            float acc[4][4];
            mma_phase<1>((const uint4*)&g_HP[mt][jg * 16][lane4],
                         su + W2HB + wrow, 0u, nx, c16b, acc);
            kreduce(su, jg, mg, lane, acc);
            if (n0 < SSZ - INSZ) {
                const int kt = 2 * ns + 4 + (jg >> 1);      // shifted ktile
                uint32_t* sp = &g_SP[nxt][mt][kt][ep_lt * 4];
#pragma unroll
                for (int h = 0; h < 2; ++h) {
                    int b = 64 * ms + 16 * mg + gr + h * 8;
                    float2 sold = *(const float2*)&g_Sf[cur][b][n0 + cown];
                    float n0v = p * sold.x + q * (acc[jg][2 * h]     + b2s[cown]);
                    float n1v = p * sold.y + q * (acc[jg][2 * h + 1] + b2s[cown + 1]);
                    *(float2*)&g_Sf[nxt][b][n0 + INSZ + cown] = make_float2(n0v, n1v);
                    sp[h + 2 * no] = pkf(n0v, n1v);
                }
            } else if (t == SEQ - 1) {
#pragma unroll
                for (int h = 0; h < 2; ++h) {
                    int b = 64 * ms + 16 * mg + gr + h * 8;
                    float2 sold = *(const float2*)&g_Sf[cur][b][n0 + cown];
                    float n0v = p * sold.x + q * (acc[jg][2 * h]     + b2s[cown]);
                    float n1v = p * sold.y + q * (acc[jg][2 * h + 1] + b2s[cown + 1]);
                    *(float2*)&out[(size_t)b * OUTSZ + (n0 - (SSZ - OUTSZ)) + cown] =
                        make_float2(n0v, n1v);
                }
            }
            // x_{t+1} injection: CTAs ns<2 fill cols [32ns, +32) of own rows
            if (t + 1 < SEQ && ns < 2) {
                const float* xp = x + (size_t)(t + 1) * BATCH * INSZ;
                for (int idx = tid; idx < 64 * 16; idx += NTHR) {
                    int row = idx >> 4, pc = idx & 15;
                    int b = 64 * ms + row, k = n0 + 2 * pc;
                    float v0 = xp[(size_t)b * INSZ + k];
                    float v1 = xp[(size_t)b * INSZ + k + 1];
                    *(float2*)&g_Sf[nxt][b][k] = make_float2(v0, v1);
                    int bt = b >> 4, rr = b & 15, c = k & 15;
                    int lt  = (rr & 7) * 4 + ((c >> 1) & 3);
                    int reg = (rr >> 3) + 2 * (c >> 3);
                    g_SP[nxt][bt][k >> 4][lt * 4 + reg] = pkf(v0, v1);
                }
            }
        }
        gbar(ep0, ++bc, cta);
    }
}

extern "C" void kernel_launch(void* const* d_in, const int* in_sizes, int n_in,
                              void* d_out, int out_size) {
    (void)in_sizes; (void)n_in; (void)out_size;
    const float* x  = (const float*)d_in[0];
    const float* W1 = (const float*)d_in[1];
    const float* b1 = (const float*)d_in[2];
    const float* W2 = (const float*)d_in[3];
    const float* b2 = (const float*)d_in[4];

    cudaFuncSetAttribute(resrnn_kernel,
                         cudaFuncAttributeMaxDynamicSharedMemorySize,
                         (int)SMEM_BYTES);
    resrnn_kernel<<<NCTA, NTHR, SMEM_BYTES>>>(x, W1, b1, W2, b2, (float*)d_out);
}